// round 15
// baseline (speedup 1.0000x reference)
#include <cuda_runtime.h>
#include <cuda_bf16.h>
#include <math.h>
#include <stdint.h>
#include <mma.h>

using namespace nvcuda;

#define BATCH 16384
typedef __nv_bfloat16 bf16;

// ---------------- scratch (static device arrays; no allocations) ----------------
__device__ float g_h400 [BATCH*400];   // base chain scratch (stream 0)
__device__ float g_h400b[BATCH*400];   // emb chain scratch (stream 1)
__device__ float g_out  [BATCH*256];
__device__ float g_tmp  [BATCH*256];
__device__ float g_emb  [BATCH*256];
__device__ float g_si   [BATCH*256];
__device__ float g_gsel [3*BATCH*64];
__device__ float g_fsel [BATCH*8];
__device__ float g_hbig [(size_t)BATCH*2048];   // [B][2048], col = m*256+n

// pre-split bf16 operands for the mod GEMM
__device__ bf16 g_outh[BATCH*256], g_outl[BATCH*256];
__device__ bf16 g_W2h [256*2048],  g_W2l [256*2048];   // [d][m*256+n] (g1*W only)

// deterministic two-stage batchnorm reductions (no atomics)
#define NPART 64
__device__ float g_psum1[NPART*256],  g_psq1[NPART*256];
__device__ float g_psum2[NPART*2048], g_psq2[NPART*2048];
__device__ float g_mean1[256],  g_istd1[256];
__device__ float g_mean2[2048], g_istd2[2048];

enum { EPI_NONE=0, EPI_RELU=1, EPI_TANH=2, EPI_MULRELU=3, EPI_DUAL=4 };

#define ASTR2 72    // A smem row stride in bf16 (144B): 32 hi | 32 lo | pad
#define BSTR2 264   // B smem row stride in bf16 (528B): 128 hi | 128 lo | pad
#define STG_LD 36

__device__ __forceinline__ uint32_t pack_hi(float v0, float v1, float& r0, float& r1) {
    bf16 h0 = __float2bfloat16(v0);
    bf16 h1 = __float2bfloat16(v1);
    r0 = v0 - __bfloat162float(h0);
    r1 = v1 - __bfloat162float(h1);
    return (uint32_t)__bfloat16_as_ushort(h0) | ((uint32_t)__bfloat16_as_ushort(h1) << 16);
}
__device__ __forceinline__ uint32_t pack_lo(float r0, float r1) {
    bf16 l0 = __float2bfloat16(r0);
    bf16 l1 = __float2bfloat16(r1);
    return (uint32_t)__bfloat16_as_ushort(l0) | ((uint32_t)__bfloat16_as_ushort(l1) << 16);
}

// =======================================================================
//  Split-BF16 TC GEMM with register prefetch:
//  pack+store smem -> sync -> load NEXT tile to regs -> compute -> sync.
//  128x128x32 tile, 256 thr, 8 warps x (64x32).
// =======================================================================
__global__ void __launch_bounds__(256,2) tgemm_tc(
    const float* __restrict__ A, const float* __restrict__ Bw,
    const float* __restrict__ bias, float* __restrict__ C,
    float* __restrict__ C2, const float* __restrict__ aux,
    int N, int K, int epi)
{
    __shared__ __align__(16) char sh[128*ASTR2*2 + 32*BSTR2*2];
    bf16* As = (bf16*)sh;
    bf16* Bs = (bf16*)(sh + 128*ASTR2*2);

    const int tid  = threadIdx.x;
    const int lane = tid & 31, wid = tid >> 5;
    const int warpM = (wid >> 2) * 64, warpN = (wid & 3) * 32;
    const int rowBase = blockIdx.y * 128, colBase = blockIdx.x * 128;

    const int aRow = tid >> 1, aKo = (tid & 1) * 16;
    const int bKr  = tid >> 3, bNo = (tid & 7) * 16;

    wmma::fragment<wmma::accumulator,16,16,16,float> acc[4][2];
    #pragma unroll
    for (int mt=0;mt<4;mt++)
        #pragma unroll
        for (int nt=0;nt<2;nt++)
            wmma::fill_fragment(acc[mt][nt], 0.f);

    float va[16], vb[16];

    // ---- initial tile load (kt = 0) ----
    {
        const float* ap = A + (size_t)(rowBase + aRow) * K + aKo;
        if (aKo + 15 < K) {
            float4 v0 = *(const float4*)(ap);
            float4 v1 = *(const float4*)(ap + 4);
            float4 v2 = *(const float4*)(ap + 8);
            float4 v3 = *(const float4*)(ap + 12);
            va[0]=v0.x; va[1]=v0.y; va[2]=v0.z; va[3]=v0.w;
            va[4]=v1.x; va[5]=v1.y; va[6]=v1.z; va[7]=v1.w;
            va[8]=v2.x; va[9]=v2.y; va[10]=v2.z; va[11]=v2.w;
            va[12]=v3.x; va[13]=v3.y; va[14]=v3.z; va[15]=v3.w;
        } else {
            #pragma unroll
            for (int e=0;e<16;e++) va[e] = (aKo + e < K) ? ap[e] : 0.f;
        }
        int gc = colBase + bNo;
        const float* bp = Bw + (size_t)bKr * N + gc;
        if (bKr < K && gc + 15 < N) {
            float4 v0 = *(const float4*)(bp);
            float4 v1 = *(const float4*)(bp + 4);
            float4 v2 = *(const float4*)(bp + 8);
            float4 v3 = *(const float4*)(bp + 12);
            vb[0]=v0.x; vb[1]=v0.y; vb[2]=v0.z; vb[3]=v0.w;
            vb[4]=v1.x; vb[5]=v1.y; vb[6]=v1.z; vb[7]=v1.w;
            vb[8]=v2.x; vb[9]=v2.y; vb[10]=v2.z; vb[11]=v2.w;
            vb[12]=v3.x; vb[13]=v3.y; vb[14]=v3.z; vb[15]=v3.w;
        } else {
            bool krow_ok = (bKr < K);
            #pragma unroll
            for (int e=0;e<16;e++) vb[e] = (krow_ok && gc + e < N) ? bp[e] : 0.f;
        }
    }

    for (int kt = 0; kt < K; kt += 32) {
        // ---- pack current regs -> smem ----
        {
            uint32_t ph[8], pl[8];
            float r0, r1;
            #pragma unroll
            for (int e=0;e<8;e++) {
                ph[e] = pack_hi(va[2*e], va[2*e+1], r0, r1);
                pl[e] = pack_lo(r0, r1);
            }
            uint4* dh = (uint4*)((char*)As + aRow*144 + aKo*2);
            dh[0] = make_uint4(ph[0],ph[1],ph[2],ph[3]);
            dh[1] = make_uint4(ph[4],ph[5],ph[6],ph[7]);
            uint4* dl = (uint4*)((char*)As + aRow*144 + 64 + aKo*2);
            dl[0] = make_uint4(pl[0],pl[1],pl[2],pl[3]);
            dl[1] = make_uint4(pl[4],pl[5],pl[6],pl[7]);
            #pragma unroll
            for (int e=0;e<8;e++) {
                ph[e] = pack_hi(vb[2*e], vb[2*e+1], r0, r1);
                pl[e] = pack_lo(r0, r1);
            }
            uint4* eh = (uint4*)((char*)Bs + bKr*528 + bNo*2);
            eh[0] = make_uint4(ph[0],ph[1],ph[2],ph[3]);
            eh[1] = make_uint4(ph[4],ph[5],ph[6],ph[7]);
            uint4* el = (uint4*)((char*)Bs + bKr*528 + 256 + bNo*2);
            el[0] = make_uint4(pl[0],pl[1],pl[2],pl[3]);
            el[1] = make_uint4(pl[4],pl[5],pl[6],pl[7]);
        }
        __syncthreads();

        // ---- prefetch NEXT tile into regs (overlaps the mma phase) ----
        int ktn = kt + 32;
        if (ktn < K) {
            const float* ap = A + (size_t)(rowBase + aRow) * K + ktn + aKo;
            if (ktn + aKo + 15 < K) {
                float4 v0 = *(const float4*)(ap);
                float4 v1 = *(const float4*)(ap + 4);
                float4 v2 = *(const float4*)(ap + 8);
                float4 v3 = *(const float4*)(ap + 12);
                va[0]=v0.x; va[1]=v0.y; va[2]=v0.z; va[3]=v0.w;
                va[4]=v1.x; va[5]=v1.y; va[6]=v1.z; va[7]=v1.w;
                va[8]=v2.x; va[9]=v2.y; va[10]=v2.z; va[11]=v2.w;
                va[12]=v3.x; va[13]=v3.y; va[14]=v3.z; va[15]=v3.w;
            } else {
                #pragma unroll
                for (int e=0;e<16;e++) va[e] = (ktn + aKo + e < K) ? ap[e] : 0.f;
            }
            int gc = colBase + bNo;
            const float* bp = Bw + (size_t)(ktn + bKr) * N + gc;
            if (ktn + bKr < K && gc + 15 < N) {
                float4 v0 = *(const float4*)(bp);
                float4 v1 = *(const float4*)(bp + 4);
                float4 v2 = *(const float4*)(bp + 8);
                float4 v3 = *(const float4*)(bp + 12);
                vb[0]=v0.x; vb[1]=v0.y; vb[2]=v0.z; vb[3]=v0.w;
                vb[4]=v1.x; vb[5]=v1.y; vb[6]=v1.z; vb[7]=v1.w;
                vb[8]=v2.x; vb[9]=v2.y; vb[10]=v2.z; vb[11]=v2.w;
                vb[12]=v3.x; vb[13]=v3.y; vb[14]=v3.z; vb[15]=v3.w;
            } else {
                bool krow_ok = (ktn + bKr < K);
                #pragma unroll
                for (int e=0;e<16;e++) vb[e] = (krow_ok && gc + e < N) ? bp[e] : 0.f;
            }
        }

        // ---- compute from smem ----
        #pragma unroll
        for (int ks=0; ks<32; ks+=16) {
            wmma::fragment<wmma::matrix_b,16,16,16,bf16,wmma::row_major> bh[2], bl[2];
            #pragma unroll
            for (int nt=0;nt<2;nt++) {
                wmma::load_matrix_sync(bh[nt], &Bs[ks*BSTR2 + warpN + nt*16],       BSTR2);
                wmma::load_matrix_sync(bl[nt], &Bs[ks*BSTR2 + 128 + warpN + nt*16], BSTR2);
            }
            #pragma unroll
            for (int mt=0;mt<4;mt++) {
                wmma::fragment<wmma::matrix_a,16,16,16,bf16,wmma::row_major> ah, al;
                wmma::load_matrix_sync(ah, &As[(warpM + mt*16)*ASTR2 + ks],      ASTR2);
                wmma::load_matrix_sync(al, &As[(warpM + mt*16)*ASTR2 + 32 + ks], ASTR2);
                #pragma unroll
                for (int nt=0;nt<2;nt++) {
                    wmma::mma_sync(acc[mt][nt], ah, bh[nt], acc[mt][nt]);
                    wmma::mma_sync(acc[mt][nt], ah, bl[nt], acc[mt][nt]);
                    wmma::mma_sync(acc[mt][nt], al, bh[nt], acc[mt][nt]);
                }
            }
        }
        __syncthreads();
    }

    if (bias == nullptr && epi == EPI_NONE) {
        #pragma unroll
        for (int mt=0; mt<4; mt++) {
            float* dst = C + (size_t)(rowBase + warpM + mt*16) * N + colBase + warpN;
            wmma::store_matrix_sync(dst,      acc[mt][0], N, wmma::mem_row_major);
            wmma::store_matrix_sync(dst + 16, acc[mt][1], N, wmma::mem_row_major);
        }
        return;
    }

    float* stg = (float*)sh + wid * (16*STG_LD);
    const int r  = lane >> 1;
    const int cb = (lane & 1) * 16;
    #pragma unroll
    for (int mt=0; mt<4; mt++) {
        wmma::store_matrix_sync(stg,      acc[mt][0], STG_LD, wmma::mem_row_major);
        wmma::store_matrix_sync(stg + 16, acc[mt][1], STG_LD, wmma::mem_row_major);
        __syncwarp();
        int row  = rowBase + warpM + mt*16 + r;
        int col0 = colBase + warpN + cb;
        if (col0 < N) {
            size_t base = (size_t)row * N + col0;
            #pragma unroll
            for (int e=0;e<16;e++) {
                float v = stg[r*STG_LD + cb + e] + bias[col0 + e];
                if      (epi == EPI_NONE)    C[base + e] = v;
                else if (epi == EPI_RELU)    C[base + e] = fmaxf(v, 0.f);
                else if (epi == EPI_TANH)    C[base + e] = tanhf(v);
                else if (epi == EPI_MULRELU) C[base + e] = fmaxf(v * aux[base + e], 0.f);
                else { C[base + e] = v; C2[base + e] = fmaxf(v, 0.f); }
            }
        }
        __syncwarp();
    }
}

// =======================================================================
//  Pre-split BF16 TC GEMM (mod einsum) with register prefetch.
// =======================================================================
__global__ void __launch_bounds__(256,2) tgemm_pre(
    const bf16* __restrict__ Ah, const bf16* __restrict__ Al,
    const bf16* __restrict__ Bh, const bf16* __restrict__ Bl,
    float* __restrict__ C, int N, int K)
{
    __shared__ __align__(16) char sh[128*ASTR2*2 + 32*BSTR2*2];
    bf16* As = (bf16*)sh;
    bf16* Bs = (bf16*)(sh + 128*ASTR2*2);

    const int tid  = threadIdx.x;
    const int wid  = tid >> 5;
    const int warpM = (wid >> 2) * 64, warpN = (wid & 3) * 32;
    const int rowBase = blockIdx.y * 128, colBase = blockIdx.x * 128;

    const int aRow = tid >> 1, aKo = (tid & 1) * 16;
    const int bKr  = tid >> 3, bNo = (tid & 7) * 16;

    wmma::fragment<wmma::accumulator,16,16,16,float> acc[4][2];
    #pragma unroll
    for (int mt=0;mt<4;mt++)
        #pragma unroll
        for (int nt=0;nt<2;nt++)
            wmma::fill_fragment(acc[mt][nt], 0.f);

    uint4 rA[4], rB[4];
    {
        const uint4* sH = (const uint4*)(Ah + (size_t)(rowBase + aRow) * K + aKo);
        const uint4* sL = (const uint4*)(Al + (size_t)(rowBase + aRow) * K + aKo);
        rA[0] = sH[0]; rA[1] = sH[1]; rA[2] = sL[0]; rA[3] = sL[1];
        const uint4* tH = (const uint4*)(Bh + (size_t)bKr * N + colBase + bNo);
        const uint4* tL = (const uint4*)(Bl + (size_t)bKr * N + colBase + bNo);
        rB[0] = tH[0]; rB[1] = tH[1]; rB[2] = tL[0]; rB[3] = tL[1];
    }

    for (int kt = 0; kt < K; kt += 32) {
        {
            uint4* dh = (uint4*)((char*)As + aRow*144 + aKo*2);
            uint4* dl = (uint4*)((char*)As + aRow*144 + 64 + aKo*2);
            dh[0] = rA[0]; dh[1] = rA[1]; dl[0] = rA[2]; dl[1] = rA[3];
            uint4* eh = (uint4*)((char*)Bs + bKr*528 + bNo*2);
            uint4* el = (uint4*)((char*)Bs + bKr*528 + 256 + bNo*2);
            eh[0] = rB[0]; eh[1] = rB[1]; el[0] = rB[2]; el[1] = rB[3];
        }
        __syncthreads();

        int ktn = kt + 32;
        if (ktn < K) {
            const uint4* sH = (const uint4*)(Ah + (size_t)(rowBase + aRow) * K + ktn + aKo);
            const uint4* sL = (const uint4*)(Al + (size_t)(rowBase + aRow) * K + ktn + aKo);
            rA[0] = sH[0]; rA[1] = sH[1]; rA[2] = sL[0]; rA[3] = sL[1];
            const uint4* tH = (const uint4*)(Bh + (size_t)(ktn + bKr) * N + colBase + bNo);
            const uint4* tL = (const uint4*)(Bl + (size_t)(ktn + bKr) * N + colBase + bNo);
            rB[0] = tH[0]; rB[1] = tH[1]; rB[2] = tL[0]; rB[3] = tL[1];
        }

        #pragma unroll
        for (int ks=0; ks<32; ks+=16) {
            wmma::fragment<wmma::matrix_b,16,16,16,bf16,wmma::row_major> bh[2], bl[2];
            #pragma unroll
            for (int nt=0;nt<2;nt++) {
                wmma::load_matrix_sync(bh[nt], &Bs[ks*BSTR2 + warpN + nt*16],       BSTR2);
                wmma::load_matrix_sync(bl[nt], &Bs[ks*BSTR2 + 128 + warpN + nt*16], BSTR2);
            }
            #pragma unroll
            for (int mt=0;mt<4;mt++) {
                wmma::fragment<wmma::matrix_a,16,16,16,bf16,wmma::row_major> ah, al;
                wmma::load_matrix_sync(ah, &As[(warpM + mt*16)*ASTR2 + ks],      ASTR2);
                wmma::load_matrix_sync(al, &As[(warpM + mt*16)*ASTR2 + 32 + ks], ASTR2);
                #pragma unroll
                for (int nt=0;nt<2;nt++) {
                    wmma::mma_sync(acc[mt][nt], ah, bh[nt], acc[mt][nt]);
                    wmma::mma_sync(acc[mt][nt], ah, bl[nt], acc[mt][nt]);
                    wmma::mma_sync(acc[mt][nt], al, bh[nt], acc[mt][nt]);
                }
            }
        }
        __syncthreads();
    }

    #pragma unroll
    for (int mt=0; mt<4; mt++) {
        float* dst = C + (size_t)(rowBase + warpM + mt*16) * N + colBase + warpN;
        wmma::store_matrix_sync(dst,      acc[mt][0], N, wmma::mem_row_major);
        wmma::store_matrix_sync(dst + 16, acc[mt][1], N, wmma::mem_row_major);
    }
}

// ---------------- split g_out*istd1 into bf16 hi/lo ----------------
__global__ void cvt_out(void)
{
    int i = blockIdx.x*256 + threadIdx.x;
    float v = g_out[i] * g_istd1[i & 255];
    bf16 h = __float2bfloat16(v);
    g_outh[i] = h;
    g_outl[i] = __float2bfloat16(v - __bfloat162float(h));
}

// ---------------- mod weights (g1 only; istd in A, shifts cancel in bn2) ----------------
__global__ void scaleW(const float* __restrict__ modW, const float* __restrict__ g1)
{
    int idx = blockIdx.x*256 + threadIdx.x;
    int d = idx >> 11;
    int c = idx & 2047;
    int m = c >> 8;
    int n = c & 255;
    float w = g1[m*256 + d] * modW[((size_t)(m*256 + d))*256 + n];
    bf16 h = __float2bfloat16(w);
    g_W2h[idx] = h;
    g_W2l[idx] = __float2bfloat16(w - __bfloat162float(h));
}

// ---------------- gumbel noise ----------------
__device__ __forceinline__ float gnoise(float u) {
    u = fminf(fmaxf(u, 1e-10f), 1.0f - 1e-7f);
    return -logf(-logf(u));
}

// =======================================================================
//  Fused select step (R9, proven).
// =======================================================================
__global__ void __launch_bounds__(256) selstep(
    const float* __restrict__ selW, const float* __restrict__ selb,
    const float* __restrict__ condW, const float* __restrict__ condb,
    const float* __restrict__ u, int it)
{
    extern __shared__ __align__(16) char dsm[];
    bf16*  A1  = (bf16*)dsm;
    bf16*  B1  = (bf16*)(dsm + 18432);
    float* STG = (float*)dsm;
    bf16*  LGT = (bf16*)(dsm + 34816);
    bf16*  B2  = (bf16*)dsm;

    const int tid  = threadIdx.x;
    const int lane = tid & 31, wid = tid >> 5;
    const int rowBase = blockIdx.x * 128;

    const int warpM1 = (wid >> 1) * 32, warpN1 = (wid & 1) * 32;
    const int aRow = tid >> 1, aKo = (tid & 1) * 16;
    const int bKr  = tid >> 3, bNo = (tid & 7) * 8;

    wmma::fragment<wmma::accumulator,16,16,16,float> acc1[2][2];
    #pragma unroll
    for (int mt=0;mt<2;mt++)
        #pragma unroll
        for (int nt=0;nt<2;nt++)
            wmma::fill_fragment(acc1[mt][nt], 0.f);

    for (int kt = 0; kt < 256; kt += 32) {
        {
            const float* ap = g_si + (size_t)(rowBase + aRow) * 256 + kt + aKo;
            float4 v0 = *(const float4*)(ap);
            float4 v1 = *(const float4*)(ap + 4);
            float4 v2 = *(const float4*)(ap + 8);
            float4 v3 = *(const float4*)(ap + 12);
            float va[16] = {v0.x,v0.y,v0.z,v0.w, v1.x,v1.y,v1.z,v1.w,
                            v2.x,v2.y,v2.z,v2.w, v3.x,v3.y,v3.z,v3.w};
            uint32_t ph[8], pl[8];
            float r0, r1;
            #pragma unroll
            for (int e=0;e<8;e++) {
                ph[e] = pack_hi(va[2*e], va[2*e+1], r0, r1);
                pl[e] = pack_lo(r0, r1);
            }
            uint4* dh = (uint4*)((char*)A1 + aRow*144 + aKo*2);
            dh[0] = make_uint4(ph[0],ph[1],ph[2],ph[3]);
            dh[1] = make_uint4(ph[4],ph[5],ph[6],ph[7]);
            uint4* dl = (uint4*)((char*)A1 + aRow*144 + 64 + aKo*2);
            dl[0] = make_uint4(pl[0],pl[1],pl[2],pl[3]);
            dl[1] = make_uint4(pl[4],pl[5],pl[6],pl[7]);
        }
        {
            const float* bp = selW + (size_t)(kt + bKr) * 64 + bNo;
            float4 w0 = *(const float4*)(bp);
            float4 w1 = *(const float4*)(bp + 4);
            float vb[8] = {w0.x,w0.y,w0.z,w0.w, w1.x,w1.y,w1.z,w1.w};
            uint32_t ph[4], pl[4];
            float r0, r1;
            #pragma unroll
            for (int e=0;e<4;e++) {
                ph[e] = pack_hi(vb[2*e], vb[2*e+1], r0, r1);
                pl[e] = pack_lo(r0, r1);
            }
            *(uint4*)((char*)B1 + bKr*272 + bNo*2)       = make_uint4(ph[0],ph[1],ph[2],ph[3]);
            *(uint4*)((char*)B1 + bKr*272 + 128 + bNo*2) = make_uint4(pl[0],pl[1],pl[2],pl[3]);
        }
        __syncthreads();

        #pragma unroll
        for (int ks=0; ks<32; ks+=16) {
            wmma::fragment<wmma::matrix_b,16,16,16,bf16,wmma::row_major> bh[2], bl[2];
            #pragma unroll
            for (int nt=0;nt<2;nt++) {
                wmma::load_matrix_sync(bh[nt], &B1[ks*136 + warpN1 + nt*16],      136);
                wmma::load_matrix_sync(bl[nt], &B1[ks*136 + 64 + warpN1 + nt*16], 136);
            }
            #pragma unroll
            for (int mt=0;mt<2;mt++) {
                wmma::fragment<wmma::matrix_a,16,16,16,bf16,wmma::row_major> ah, al;
                wmma::load_matrix_sync(ah, &A1[(warpM1 + mt*16)*72 + ks],      72);
                wmma::load_matrix_sync(al, &A1[(warpM1 + mt*16)*72 + 32 + ks], 72);
                #pragma unroll
                for (int nt=0;nt<2;nt++) {
                    wmma::mma_sync(acc1[mt][nt], ah, bh[nt], acc1[mt][nt]);
                    wmma::mma_sync(acc1[mt][nt], ah, bl[nt], acc1[mt][nt]);
                    wmma::mma_sync(acc1[mt][nt], al, bh[nt], acc1[mt][nt]);
                }
            }
        }
        __syncthreads();
    }

    #pragma unroll
    for (int mt=0;mt<2;mt++)
        #pragma unroll
        for (int nt=0;nt<2;nt++)
            wmma::store_matrix_sync(&STG[(warpM1 + mt*16)*68 + warpN1 + nt*16],
                                    acc1[mt][nt], 68, wmma::mem_row_major);
    __syncthreads();

    {
        int row = tid >> 1, c0 = (tid & 1) * 32;
        #pragma unroll
        for (int e=0;e<32;e++) {
            int col = c0 + e;
            float v = STG[row*68 + col];
            v = tanhf(v + selb[col]);
            STG[row*68 + col] = v;
            bf16 h = __float2bfloat16(v);
            bf16 l = __float2bfloat16(v - __bfloat162float(h));
            LGT[row*136 + col]      = h;
            LGT[row*136 + 64 + col] = l;
        }
    }
    __syncthreads();

    #pragma unroll
    for (int j=0;j<4;j++) {
        int gid = tid*4 + j;
        int row = gid >> 3, mg = gid & 7;
        int b = rowBase + row;
        const float* up = u + (size_t)b*192 + it*64 + mg*8;
        float z[8]; float mx = -3.4e38f;
        #pragma unroll
        for (int k=0;k<8;k++){ z[k] = STG[row*68 + mg*8 + k] + gnoise(up[k]); mx = fmaxf(mx, z[k]); }
        float s = 0.f;
        #pragma unroll
        for (int k=0;k<8;k++){ z[k] = expf(z[k]-mx); s += z[k]; }
        float inv = 1.f/s;
        float* op = g_gsel + (size_t)it*BATCH*64 + (size_t)b*64 + mg*8;
        #pragma unroll
        for (int k=0;k<8;k++) op[k] = z[k]*inv;
    }
    __syncthreads();

    const int warpM2 = (wid >> 2) * 64, warpN2 = (wid & 3) * 32;
    const int bk2 = tid >> 2, bn2 = (tid & 3) * 32;
    const int r  = lane >> 1, cb = (lane & 1) * 16;

    for (int nh = 0; nh < 2; nh++) {
        {
            const float* bp = condW + (size_t)bk2*256 + nh*128 + bn2;
            float vb[32];
            #pragma unroll
            for (int q=0;q<8;q++) {
                float4 w = *(const float4*)(bp + q*4);
                vb[q*4+0]=w.x; vb[q*4+1]=w.y; vb[q*4+2]=w.z; vb[q*4+3]=w.w;
            }
            uint32_t ph[16], pl[16];
            float r0, r1;
            #pragma unroll
            for (int e=0;e<16;e++) {
                ph[e] = pack_hi(vb[2*e], vb[2*e+1], r0, r1);
                pl[e] = pack_lo(r0, r1);
            }
            uint4* dh = (uint4*)((char*)B2 + bk2*528 + bn2*2);
            uint4* dl = (uint4*)((char*)B2 + bk2*528 + 256 + bn2*2);
            #pragma unroll
            for (int q=0;q<4;q++) {
                dh[q] = make_uint4(ph[q*4],ph[q*4+1],ph[q*4+2],ph[q*4+3]);
                dl[q] = make_uint4(pl[q*4],pl[q*4+1],pl[q*4+2],pl[q*4+3]);
            }
        }
        __syncthreads();

        wmma::fragment<wmma::accumulator,16,16,16,float> acc2[4][2];
        #pragma unroll
        for (int mt=0;mt<4;mt++)
            #pragma unroll
            for (int nt=0;nt<2;nt++)
                wmma::fill_fragment(acc2[mt][nt], 0.f);

        #pragma unroll
        for (int ks=0; ks<64; ks+=16) {
            wmma::fragment<wmma::matrix_b,16,16,16,bf16,wmma::row_major> bh[2], bl[2];
            #pragma unroll
            for (int nt=0;nt<2;nt++) {
                wmma::load_matrix_sync(bh[nt], &B2[ks*264 + warpN2 + nt*16],       264);
                wmma::load_matrix_sync(bl[nt], &B2[ks*264 + 128 + warpN2 + nt*16], 264);
            }
            #pragma unroll
            for (int mt=0;mt<4;mt++) {
                wmma::fragment<wmma::matrix_a,16,16,16,bf16,wmma::row_major> ah, al;
                wmma::load_matrix_sync(ah, &LGT[(warpM2 + mt*16)*136 + ks],      136);
                wmma::load_matrix_sync(al, &LGT[(warpM2 + mt*16)*136 + 64 + ks], 136);
                #pragma unroll
                for (int nt=0;nt<2;nt++) {
                    wmma::mma_sync(acc2[mt][nt], ah, bh[nt], acc2[mt][nt]);
                    wmma::mma_sync(acc2[mt][nt], ah, bl[nt], acc2[mt][nt]);
                    wmma::mma_sync(acc2[mt][nt], al, bh[nt], acc2[mt][nt]);
                }
            }
        }
        __syncthreads();

        float* stg2 = (float*)dsm + wid * (16*STG_LD);
        #pragma unroll
        for (int mt=0; mt<4; mt++) {
            wmma::store_matrix_sync(stg2,      acc2[mt][0], STG_LD, wmma::mem_row_major);
            wmma::store_matrix_sync(stg2 + 16, acc2[mt][1], STG_LD, wmma::mem_row_major);
            __syncwarp();
            int row  = rowBase + warpM2 + mt*16 + r;
            int col0 = nh*128 + warpN2 + cb;
            size_t base = (size_t)row * 256 + col0;
            #pragma unroll
            for (int e=0;e<16;e++) {
                float v = stg2[r*STG_LD + cb + e] + condb[col0 + e];
                v *= g_emb[base + e];
                g_si[base + e] = fmaxf(v, 0.f);
            }
            __syncwarp();
        }
        __syncthreads();
    }
}

// ---------------- batchnorm stats (deterministic 2-stage) ----------------
__global__ void colstats(const float* __restrict__ X,
                         float* __restrict__ psum, float* __restrict__ psq,
                         int ncols)
{
    int c = blockIdx.x*256 + threadIdx.x;
    int rpb = BATCH / NPART;
    int r0  = blockIdx.y * rpb;
    float s = 0.f, q = 0.f;
    for (int r = r0; r < r0 + rpb; r++) {
        float v = X[(size_t)r*ncols + c];
        s += v; q += v*v;
    }
    psum[(size_t)blockIdx.y*ncols + c] = s;
    psq [(size_t)blockIdx.y*ncols + c] = q;
}

__global__ void bnfinal(const float* __restrict__ psum, const float* __restrict__ psq,
                        float* __restrict__ mean, float* __restrict__ istd, int n)
{
    int i = blockIdx.x*blockDim.x + threadIdx.x;
    if (i >= n) return;
    float s = 0.f, q = 0.f;
    for (int p = 0; p < NPART; p++) { s += psum[(size_t)p*n + i]; q += psq[(size_t)p*n + i]; }
    float mu  = s * (1.f/BATCH);
    float var = q * (1.f/BATCH) - mu*mu;
    mean[i] = mu;
    istd[i] = rsqrtf(var + 1e-5f);
}

// ---------------- final select logits + fused gumbel ----------------
__global__ void __launch_bounds__(256) gemm_selF(
    const float* __restrict__ W, const float* __restrict__ bias,
    const float* __restrict__ u)
{
    __shared__ float Ws[2048];
    int tid = threadIdx.x;
    for (int idx = tid; idx < 2048; idx += 256) Ws[idx] = W[idx];
    __syncthreads();
    int b = blockIdx.x*32 + (tid >> 3);
    int n = tid & 7;
    const float* ap = g_si + (size_t)b*256;
    float acc = bias[n];
    #pragma unroll 8
    for (int k=0;k<256;k++) acc += ap[k]*Ws[k*8+n];
    float z = acc + gnoise(u[b*8 + n]);
    float mx = z;
    #pragma unroll
    for (int o=1;o<8;o<<=1) mx = fmaxf(mx, __shfl_xor_sync(0xffffffff, mx, o));
    float e = expf(z - mx);
    float s = e;
    #pragma unroll
    for (int o=1;o<8;o<<=1) s += __shfl_xor_sync(0xffffffff, s, o);
    g_fsel[b*8 + n] = e / s;
}

// ---------------- fused bn2 + select cascade + final select + last GEMM ----------------
__global__ void __launch_bounds__(256) cascade(
    const float* __restrict__ g2, const float* __restrict__ b2,
    const float* __restrict__ lastW, const float* __restrict__ lastb,
    float* __restrict__ out)
{
    int b = blockIdx.x;
    int tid = threadIdx.x;
    __shared__ float Ssh[64];
    __shared__ float fs[8];
    __shared__ float ov[256];

    float p[8];
    #pragma unroll
    for (int m=0;m<8;m++) {
        int c = m*256 + tid;
        float v = g_hbig[(size_t)b*2048 + c];
        p[m] = (v - g_mean2[c]) * g_istd2[c] * g2[c] + b2[c];
    }

    for (int l=0;l<3;l++) {
        if (tid < 64) Ssh[tid] = g_gsel[(size_t)(2-l)*BATCH*64 + (size_t)b*64 + tid];
        __syncthreads();
        float np[8];
        #pragma unroll
        for (int m=0;m<8;m++) {
            float a = 0.f;
            #pragma unroll
            for (int k=0;k<8;k++) a += Ssh[m*8+k]*p[k];
            np[m] = fmaxf(a, 0.f);
        }
        #pragma unroll
        for (int m=0;m<8;m++) p[m] = np[m];
        __syncthreads();
    }

    if (tid < 8) fs[tid] = g_fsel[b*8+tid];
    __syncthreads();
    float o = 0.f;
    #pragma unroll
    for (int m=0;m<8;m++) o += fs[m]*p[m];
    ov[tid] = o;
    __syncthreads();

    if (tid < 18) {
        float acc = lastb[tid];
        for (int k=0;k<256;k++) acc += ov[k]*lastW[k*18+tid];
        out[(size_t)b*18 + tid] = acc;
    }
}

// ---------------- launch ----------------
extern "C" void kernel_launch(void* const* d_in, const int* in_sizes, int n_in,
                              void* d_out, int out_size)
{
    const float* x       = (const float*)d_in[0];
    const float* embIn   = (const float*)d_in[1];
    const float* u_sel   = (const float*)d_in[2];
    const float* u_fin   = (const float*)d_in[3];
    const float* base_W0 = (const float*)d_in[4];
    const float* base_b0 = (const float*)d_in[5];
    const float* base_W1 = (const float*)d_in[6];
    const float* base_b1 = (const float*)d_in[7];
    const float* em_W0   = (const float*)d_in[8];
    const float* em_b0   = (const float*)d_in[9];
    const float* gat_W0  = (const float*)d_in[10];
    const float* gat_b0  = (const float*)d_in[11];
    const float* gat_W1  = (const float*)d_in[12];
    const float* gat_b1  = (const float*)d_in[13];
    const float* sel_W   = (const float*)d_in[14];
    const float* sel_b   = (const float*)d_in[15];
    const float* selF_W  = (const float*)d_in[16];
    const float* selF_b  = (const float*)d_in[17];
    const float* cond_W  = (const float*)d_in[18];
    const float* cond_b  = (const float*)d_in[19];
    const float* mod_W   = (const float*)d_in[20];
    const float* last_W  = (const float*)d_in[22];
    const float* last_b  = (const float*)d_in[23];
    const float* bn1_g   = (const float*)d_in[24];
    const float* bn2_g   = (const float*)d_in[26];
    const float* bn2_b   = (const float*)d_in[27];
    float* out = (float*)d_out;

    float *p_h400, *p_h400b, *p_out, *p_tmp, *p_emb, *p_si, *p_hbig;
    float *p_psum1, *p_psq1, *p_psum2, *p_psq2, *p_mean1, *p_istd1, *p_mean2, *p_istd2;
    bf16 *p_outh, *p_outl, *p_W2h, *p_W2l;
    cudaGetSymbolAddress((void**)&p_h400,  g_h400);
    cudaGetSymbolAddress((void**)&p_h400b, g_h400b);
    cudaGetSymbolAddress((void**)&p_out,   g_out);
    cudaGetSymbolAddress((void**)&p_tmp,   g_tmp);
    cudaGetSymbolAddress((void**)&p_emb,   g_emb);
    cudaGetSymbolAddress((void**)&p_si,    g_si);
    cudaGetSymbolAddress((void**)&p_hbig,  g_hbig);
    cudaGetSymbolAddress((void**)&p_psum1, g_psum1);
    cudaGetSymbolAddress((void**)&p_psq1,  g_psq1);
    cudaGetSymbolAddress((void**)&p_psum2, g_psum2);
    cudaGetSymbolAddress((void**)&p_psq2,  g_psq2);
    cudaGetSymbolAddress((void**)&p_mean1, g_mean1);
    cudaGetSymbolAddress((void**)&p_istd1, g_istd1);
    cudaGetSymbolAddress((void**)&p_mean2, g_mean2);
    cudaGetSymbolAddress((void**)&p_istd2, g_istd2);
    cudaGetSymbolAddress((void**)&p_outh,  g_outh);
    cudaGetSymbolAddress((void**)&p_outl,  g_outl);
    cudaGetSymbolAddress((void**)&p_W2h,   g_W2h);
    cudaGetSymbolAddress((void**)&p_W2l,   g_W2l);

    cudaFuncSetAttribute(selstep, cudaFuncAttributeMaxDynamicSharedMemorySize, 69632);

    static cudaStream_t s1 = nullptr;
    static cudaEvent_t evFork = nullptr, evJoin = nullptr, evW = nullptr;
    if (s1 == nullptr) {
        cudaStreamCreateWithFlags(&s1, cudaStreamNonBlocking);
        cudaEventCreateWithFlags(&evFork, cudaEventDisableTiming);
        cudaEventCreateWithFlags(&evJoin, cudaEventDisableTiming);
        cudaEventCreateWithFlags(&evW,    cudaEventDisableTiming);
    }

    dim3 blk(256);
    auto grid2 = [](int N){ return dim3((unsigned)((N+127)/128), BATCH/128); };

    // ---- fork ----
    cudaEventRecord(evFork, 0);
    cudaStreamWaitEvent(s1, evFork, 0);

    // ===== branch B (stream 1): W2 prep + emb chain + select loop + selF =====
    scaleW<<<2048, blk, 0, s1>>>(mod_W, bn1_g);     // no batch-data deps
    cudaEventRecord(evW, s1);
    tgemm_tc<<<grid2(400), blk, 0, s1>>>(embIn,   em_W0,  em_b0,  p_h400b, nullptr, nullptr, 400, 128, EPI_RELU);
    tgemm_tc<<<grid2(256), blk, 0, s1>>>(p_h400b, gat_W0, gat_b0, p_tmp,   nullptr, nullptr, 256, 400, EPI_RELU);
    tgemm_tc<<<grid2(256), blk, 0, s1>>>(p_tmp,   gat_W1, gat_b1, p_emb,   p_si,    nullptr, 256, 256, EPI_DUAL);
    for (int i = 0; i < 3; i++) {
        selstep<<<BATCH/128, blk, 69632, s1>>>(sel_W + (size_t)i*256*64, sel_b + i*64,
                                               cond_W + (size_t)i*64*256, cond_b + i*256,
                                               u_sel, i);
    }
    gemm_selF<<<BATCH/32, blk, 0, s1>>>(selF_W, selF_b, u_fin);
    cudaEventRecord(evJoin, s1);

    // ===== branch A (main stream): base chain -> bn1 -> cvt -> mod GEMM -> bn2 =====
    tgemm_tc<<<grid2(400), blk, 0, 0>>>(x,      base_W0, base_b0, p_h400, nullptr, nullptr, 400, 128, EPI_RELU);
    tgemm_tc<<<grid2(256), blk, 0, 0>>>(p_h400, base_W1, base_b1, p_out,  nullptr, nullptr, 256, 400, EPI_NONE);
    colstats<<<dim3(1, NPART), blk, 0, 0>>>(p_out, p_psum1, p_psq1, 256);
    bnfinal<<<1, blk, 0, 0>>>(p_psum1, p_psq1, p_mean1, p_istd1, 256);
    cvt_out<<<BATCH, blk, 0, 0>>>();                 // out*istd1, split
    cudaStreamWaitEvent(0, evW, 0);                  // W2 ready
    tgemm_pre<<<grid2(2048), blk, 0, 0>>>(p_outh, p_outl, p_W2h, p_W2l, p_hbig, 2048, 256);
    colstats<<<dim3(8, NPART), blk, 0, 0>>>(p_hbig, p_psum2, p_psq2, 2048);
    bnfinal<<<8, blk, 0, 0>>>(p_psum2, p_psq2, p_mean2, p_istd2, 2048);

    // ---- join, then final fused kernel ----
    cudaStreamWaitEvent(0, evJoin, 0);
    cascade<<<BATCH, blk, 0, 0>>>(bn2_g, bn2_b, last_W, last_b, out);
}

// round 16
// speedup vs baseline: 1.0493x; 1.0493x over previous
#include <cuda_runtime.h>
#include <cuda_bf16.h>
#include <math.h>
#include <stdint.h>
#include <mma.h>

using namespace nvcuda;

#define BATCH 16384
typedef __nv_bfloat16 bf16;

// ---------------- scratch (static device arrays; no allocations) ----------------
__device__ float g_h400 [BATCH*400];   // base chain scratch (stream 0)
__device__ float g_h400b[BATCH*400];   // emb chain scratch (stream 1)
__device__ float g_out  [BATCH*256];
__device__ float g_tmp  [BATCH*256];
__device__ float g_emb  [BATCH*256];
__device__ float g_si   [BATCH*256];
__device__ float g_gsel [3*BATCH*64];
__device__ float g_fsel [BATCH*8];
__device__ float g_hbig [(size_t)BATCH*2048];   // [B][2048], col = m*256+n

// pre-split bf16 operands for the mod GEMM
__device__ bf16 g_outh[BATCH*256], g_outl[BATCH*256];
__device__ bf16 g_W2h [256*2048],  g_W2l [256*2048];   // [d][m*256+n] (g1*W only)

// deterministic two-stage batchnorm reductions (no atomics)
#define NPART 64
__device__ float g_psum1[NPART*256],  g_psq1[NPART*256];
__device__ float g_psum2[NPART*2048], g_psq2[NPART*2048];
__device__ float g_mean1[256],  g_istd1[256];
__device__ float g_mean2[2048], g_istd2[2048];

enum { EPI_NONE=0, EPI_RELU=1, EPI_TANH=2, EPI_MULRELU=3, EPI_DUAL=4 };

#define ASTR2 72    // A smem row stride in bf16 (144B): 32 hi | 32 lo | pad
#define BSTR2 264   // B smem row stride in bf16 (528B): 128 hi | 128 lo | pad
#define STG_LD 36

__device__ __forceinline__ uint32_t pack_hi(float v0, float v1, float& r0, float& r1) {
    bf16 h0 = __float2bfloat16(v0);
    bf16 h1 = __float2bfloat16(v1);
    r0 = v0 - __bfloat162float(h0);
    r1 = v1 - __bfloat162float(h1);
    return (uint32_t)__bfloat16_as_ushort(h0) | ((uint32_t)__bfloat16_as_ushort(h1) << 16);
}
__device__ __forceinline__ uint32_t pack_lo(float r0, float r1) {
    bf16 l0 = __float2bfloat16(r0);
    bf16 l1 = __float2bfloat16(r1);
    return (uint32_t)__bfloat16_as_ushort(l0) | ((uint32_t)__bfloat16_as_ushort(l1) << 16);
}

// =======================================================================
//  Split-BF16 TC GEMM (R9/R14, proven — NO prefetch): fp32 inputs
//  converted in-kernel. 128x128x32 tile, 256 thr, 8 warps x (64x32).
// =======================================================================
__global__ void __launch_bounds__(256,2) tgemm_tc(
    const float* __restrict__ A, const float* __restrict__ Bw,
    const float* __restrict__ bias, float* __restrict__ C,
    float* __restrict__ C2, const float* __restrict__ aux,
    int N, int K, int epi)
{
    __shared__ __align__(16) char sh[128*ASTR2*2 + 32*BSTR2*2];
    bf16* As = (bf16*)sh;
    bf16* Bs = (bf16*)(sh + 128*ASTR2*2);

    const int tid  = threadIdx.x;
    const int lane = tid & 31, wid = tid >> 5;
    const int warpM = (wid >> 2) * 64, warpN = (wid & 3) * 32;
    const int rowBase = blockIdx.y * 128, colBase = blockIdx.x * 128;

    const int aRow = tid >> 1, aKo = (tid & 1) * 16;
    const int bKr  = tid >> 3, bNo = (tid & 7) * 16;

    wmma::fragment<wmma::accumulator,16,16,16,float> acc[4][2];
    #pragma unroll
    for (int mt=0;mt<4;mt++)
        #pragma unroll
        for (int nt=0;nt<2;nt++)
            wmma::fill_fragment(acc[mt][nt], 0.f);

    for (int kt = 0; kt < K; kt += 32) {
        {
            float va[16];
            const float* ap = A + (size_t)(rowBase + aRow) * K + kt + aKo;
            if (kt + aKo + 15 < K) {
                float4 v0 = *(const float4*)(ap);
                float4 v1 = *(const float4*)(ap + 4);
                float4 v2 = *(const float4*)(ap + 8);
                float4 v3 = *(const float4*)(ap + 12);
                va[0]=v0.x; va[1]=v0.y; va[2]=v0.z; va[3]=v0.w;
                va[4]=v1.x; va[5]=v1.y; va[6]=v1.z; va[7]=v1.w;
                va[8]=v2.x; va[9]=v2.y; va[10]=v2.z; va[11]=v2.w;
                va[12]=v3.x; va[13]=v3.y; va[14]=v3.z; va[15]=v3.w;
            } else {
                #pragma unroll
                for (int e=0;e<16;e++) va[e] = (kt + aKo + e < K) ? ap[e] : 0.f;
            }
            uint32_t ph[8], pl[8];
            float r0, r1;
            #pragma unroll
            for (int e=0;e<8;e++) {
                ph[e] = pack_hi(va[2*e], va[2*e+1], r0, r1);
                pl[e] = pack_lo(r0, r1);
            }
            uint4* dh = (uint4*)((char*)As + aRow*144 + aKo*2);
            dh[0] = make_uint4(ph[0],ph[1],ph[2],ph[3]);
            dh[1] = make_uint4(ph[4],ph[5],ph[6],ph[7]);
            uint4* dl = (uint4*)((char*)As + aRow*144 + 64 + aKo*2);
            dl[0] = make_uint4(pl[0],pl[1],pl[2],pl[3]);
            dl[1] = make_uint4(pl[4],pl[5],pl[6],pl[7]);
        }
        {
            float vb[16];
            int gc = colBase + bNo;
            const float* bp = Bw + (size_t)(kt + bKr) * N + gc;
            if (kt + bKr < K && gc + 15 < N) {
                float4 v0 = *(const float4*)(bp);
                float4 v1 = *(const float4*)(bp + 4);
                float4 v2 = *(const float4*)(bp + 8);
                float4 v3 = *(const float4*)(bp + 12);
                vb[0]=v0.x; vb[1]=v0.y; vb[2]=v0.z; vb[3]=v0.w;
                vb[4]=v1.x; vb[5]=v1.y; vb[6]=v1.z; vb[7]=v1.w;
                vb[8]=v2.x; vb[9]=v2.y; vb[10]=v2.z; vb[11]=v2.w;
                vb[12]=v3.x; vb[13]=v3.y; vb[14]=v3.z; vb[15]=v3.w;
            } else {
                bool krow_ok = (kt + bKr < K);
                #pragma unroll
                for (int e=0;e<16;e++) vb[e] = (krow_ok && gc + e < N) ? bp[e] : 0.f;
            }
            uint32_t ph[8], pl[8];
            float r0, r1;
            #pragma unroll
            for (int e=0;e<8;e++) {
                ph[e] = pack_hi(vb[2*e], vb[2*e+1], r0, r1);
                pl[e] = pack_lo(r0, r1);
            }
            uint4* dh = (uint4*)((char*)Bs + bKr*528 + bNo*2);
            dh[0] = make_uint4(ph[0],ph[1],ph[2],ph[3]);
            dh[1] = make_uint4(ph[4],ph[5],ph[6],ph[7]);
            uint4* dl = (uint4*)((char*)Bs + bKr*528 + 256 + bNo*2);
            dl[0] = make_uint4(pl[0],pl[1],pl[2],pl[3]);
            dl[1] = make_uint4(pl[4],pl[5],pl[6],pl[7]);
        }
        __syncthreads();

        #pragma unroll
        for (int ks=0; ks<32; ks+=16) {
            wmma::fragment<wmma::matrix_b,16,16,16,bf16,wmma::row_major> bh[2], bl[2];
            #pragma unroll
            for (int nt=0;nt<2;nt++) {
                wmma::load_matrix_sync(bh[nt], &Bs[ks*BSTR2 + warpN + nt*16],       BSTR2);
                wmma::load_matrix_sync(bl[nt], &Bs[ks*BSTR2 + 128 + warpN + nt*16], BSTR2);
            }
            #pragma unroll
            for (int mt=0;mt<4;mt++) {
                wmma::fragment<wmma::matrix_a,16,16,16,bf16,wmma::row_major> ah, al;
                wmma::load_matrix_sync(ah, &As[(warpM + mt*16)*ASTR2 + ks],      ASTR2);
                wmma::load_matrix_sync(al, &As[(warpM + mt*16)*ASTR2 + 32 + ks], ASTR2);
                #pragma unroll
                for (int nt=0;nt<2;nt++) {
                    wmma::mma_sync(acc[mt][nt], ah, bh[nt], acc[mt][nt]);
                    wmma::mma_sync(acc[mt][nt], ah, bl[nt], acc[mt][nt]);
                    wmma::mma_sync(acc[mt][nt], al, bh[nt], acc[mt][nt]);
                }
            }
        }
        __syncthreads();
    }

    if (bias == nullptr && epi == EPI_NONE) {
        #pragma unroll
        for (int mt=0; mt<4; mt++) {
            float* dst = C + (size_t)(rowBase + warpM + mt*16) * N + colBase + warpN;
            wmma::store_matrix_sync(dst,      acc[mt][0], N, wmma::mem_row_major);
            wmma::store_matrix_sync(dst + 16, acc[mt][1], N, wmma::mem_row_major);
        }
        return;
    }

    float* stg = (float*)sh + wid * (16*STG_LD);
    const int r  = lane >> 1;
    const int cb = (lane & 1) * 16;
    #pragma unroll
    for (int mt=0; mt<4; mt++) {
        wmma::store_matrix_sync(stg,      acc[mt][0], STG_LD, wmma::mem_row_major);
        wmma::store_matrix_sync(stg + 16, acc[mt][1], STG_LD, wmma::mem_row_major);
        __syncwarp();
        int row  = rowBase + warpM + mt*16 + r;
        int col0 = colBase + warpN + cb;
        if (col0 < N) {
            size_t base = (size_t)row * N + col0;
            #pragma unroll
            for (int e=0;e<16;e++) {
                float v = stg[r*STG_LD + cb + e] + bias[col0 + e];
                if      (epi == EPI_NONE)    C[base + e] = v;
                else if (epi == EPI_RELU)    C[base + e] = fmaxf(v, 0.f);
                else if (epi == EPI_TANH)    C[base + e] = tanhf(v);
                else if (epi == EPI_MULRELU) C[base + e] = fmaxf(v * aux[base + e], 0.f);
                else { C[base + e] = v; C2[base + e] = fmaxf(v, 0.f); }
            }
        }
        __syncwarp();
    }
}

// =======================================================================
//  Pre-split BF16 TC GEMM for the mod einsum (R13, proven — NO prefetch):
//  pure uint4 tile loads, direct-store epilogue.
// =======================================================================
__global__ void __launch_bounds__(256,2) tgemm_pre(
    const bf16* __restrict__ Ah, const bf16* __restrict__ Al,
    const bf16* __restrict__ Bh, const bf16* __restrict__ Bl,
    float* __restrict__ C, int N, int K)
{
    __shared__ __align__(16) char sh[128*ASTR2*2 + 32*BSTR2*2];
    bf16* As = (bf16*)sh;
    bf16* Bs = (bf16*)(sh + 128*ASTR2*2);

    const int tid  = threadIdx.x;
    const int wid  = tid >> 5;
    const int warpM = (wid >> 2) * 64, warpN = (wid & 3) * 32;
    const int rowBase = blockIdx.y * 128, colBase = blockIdx.x * 128;

    const int aRow = tid >> 1, aKo = (tid & 1) * 16;
    const int bKr  = tid >> 3, bNo = (tid & 7) * 16;

    wmma::fragment<wmma::accumulator,16,16,16,float> acc[4][2];
    #pragma unroll
    for (int mt=0;mt<4;mt++)
        #pragma unroll
        for (int nt=0;nt<2;nt++)
            wmma::fill_fragment(acc[mt][nt], 0.f);

    for (int kt = 0; kt < K; kt += 32) {
        {
            const uint4* sH = (const uint4*)(Ah + (size_t)(rowBase + aRow) * K + kt + aKo);
            const uint4* sL = (const uint4*)(Al + (size_t)(rowBase + aRow) * K + kt + aKo);
            uint4* dh = (uint4*)((char*)As + aRow*144 + aKo*2);
            uint4* dl = (uint4*)((char*)As + aRow*144 + 64 + aKo*2);
            dh[0] = sH[0]; dh[1] = sH[1];
            dl[0] = sL[0]; dl[1] = sL[1];
        }
        {
            const uint4* sH = (const uint4*)(Bh + (size_t)(kt + bKr) * N + colBase + bNo);
            const uint4* sL = (const uint4*)(Bl + (size_t)(kt + bKr) * N + colBase + bNo);
            uint4* dh = (uint4*)((char*)Bs + bKr*528 + bNo*2);
            uint4* dl = (uint4*)((char*)Bs + bKr*528 + 256 + bNo*2);
            dh[0] = sH[0]; dh[1] = sH[1];
            dl[0] = sL[0]; dl[1] = sL[1];
        }
        __syncthreads();

        #pragma unroll
        for (int ks=0; ks<32; ks+=16) {
            wmma::fragment<wmma::matrix_b,16,16,16,bf16,wmma::row_major> bh[2], bl[2];
            #pragma unroll
            for (int nt=0;nt<2;nt++) {
                wmma::load_matrix_sync(bh[nt], &Bs[ks*BSTR2 + warpN + nt*16],       BSTR2);
                wmma::load_matrix_sync(bl[nt], &Bs[ks*BSTR2 + 128 + warpN + nt*16], BSTR2);
            }
            #pragma unroll
            for (int mt=0;mt<4;mt++) {
                wmma::fragment<wmma::matrix_a,16,16,16,bf16,wmma::row_major> ah, al;
                wmma::load_matrix_sync(ah, &As[(warpM + mt*16)*ASTR2 + ks],      ASTR2);
                wmma::load_matrix_sync(al, &As[(warpM + mt*16)*ASTR2 + 32 + ks], ASTR2);
                #pragma unroll
                for (int nt=0;nt<2;nt++) {
                    wmma::mma_sync(acc[mt][nt], ah, bh[nt], acc[mt][nt]);
                    wmma::mma_sync(acc[mt][nt], ah, bl[nt], acc[mt][nt]);
                    wmma::mma_sync(acc[mt][nt], al, bh[nt], acc[mt][nt]);
                }
            }
        }
        __syncthreads();
    }

    #pragma unroll
    for (int mt=0; mt<4; mt++) {
        float* dst = C + (size_t)(rowBase + warpM + mt*16) * N + colBase + warpN;
        wmma::store_matrix_sync(dst,      acc[mt][0], N, wmma::mem_row_major);
        wmma::store_matrix_sync(dst + 16, acc[mt][1], N, wmma::mem_row_major);
    }
}

// ---------------- split g_out*istd1 into bf16 hi/lo ----------------
__global__ void cvt_out(void)
{
    int i = blockIdx.x*256 + threadIdx.x;
    float v = g_out[i] * g_istd1[i & 255];
    bf16 h = __float2bfloat16(v);
    g_outh[i] = h;
    g_outl[i] = __float2bfloat16(v - __bfloat162float(h));
}

// ---------------- mod weights (g1 only; istd in A, shifts cancel in bn2) ----------------
__global__ void scaleW(const float* __restrict__ modW, const float* __restrict__ g1)
{
    int idx = blockIdx.x*256 + threadIdx.x;
    int d = idx >> 11;
    int c = idx & 2047;
    int m = c >> 8;
    int n = c & 255;
    float w = g1[m*256 + d] * modW[((size_t)(m*256 + d))*256 + n];
    bf16 h = __float2bfloat16(w);
    g_W2h[idx] = h;
    g_W2l[idx] = __float2bfloat16(w - __bfloat162float(h));
}

// ---------------- gumbel noise ----------------
__device__ __forceinline__ float gnoise(float u) {
    u = fminf(fmaxf(u, 1e-10f), 1.0f - 1e-7f);
    return -logf(-logf(u));
}

// =======================================================================
//  Fused select step (R9, proven).
// =======================================================================
__global__ void __launch_bounds__(256) selstep(
    const float* __restrict__ selW, const float* __restrict__ selb,
    const float* __restrict__ condW, const float* __restrict__ condb,
    const float* __restrict__ u, int it)
{
    extern __shared__ __align__(16) char dsm[];
    bf16*  A1  = (bf16*)dsm;
    bf16*  B1  = (bf16*)(dsm + 18432);
    float* STG = (float*)dsm;
    bf16*  LGT = (bf16*)(dsm + 34816);
    bf16*  B2  = (bf16*)dsm;

    const int tid  = threadIdx.x;
    const int lane = tid & 31, wid = tid >> 5;
    const int rowBase = blockIdx.x * 128;

    const int warpM1 = (wid >> 1) * 32, warpN1 = (wid & 1) * 32;
    const int aRow = tid >> 1, aKo = (tid & 1) * 16;
    const int bKr  = tid >> 3, bNo = (tid & 7) * 8;

    wmma::fragment<wmma::accumulator,16,16,16,float> acc1[2][2];
    #pragma unroll
    for (int mt=0;mt<2;mt++)
        #pragma unroll
        for (int nt=0;nt<2;nt++)
            wmma::fill_fragment(acc1[mt][nt], 0.f);

    for (int kt = 0; kt < 256; kt += 32) {
        {
            const float* ap = g_si + (size_t)(rowBase + aRow) * 256 + kt + aKo;
            float4 v0 = *(const float4*)(ap);
            float4 v1 = *(const float4*)(ap + 4);
            float4 v2 = *(const float4*)(ap + 8);
            float4 v3 = *(const float4*)(ap + 12);
            float va[16] = {v0.x,v0.y,v0.z,v0.w, v1.x,v1.y,v1.z,v1.w,
                            v2.x,v2.y,v2.z,v2.w, v3.x,v3.y,v3.z,v3.w};
            uint32_t ph[8], pl[8];
            float r0, r1;
            #pragma unroll
            for (int e=0;e<8;e++) {
                ph[e] = pack_hi(va[2*e], va[2*e+1], r0, r1);
                pl[e] = pack_lo(r0, r1);
            }
            uint4* dh = (uint4*)((char*)A1 + aRow*144 + aKo*2);
            dh[0] = make_uint4(ph[0],ph[1],ph[2],ph[3]);
            dh[1] = make_uint4(ph[4],ph[5],ph[6],ph[7]);
            uint4* dl = (uint4*)((char*)A1 + aRow*144 + 64 + aKo*2);
            dl[0] = make_uint4(pl[0],pl[1],pl[2],pl[3]);
            dl[1] = make_uint4(pl[4],pl[5],pl[6],pl[7]);
        }
        {
            const float* bp = selW + (size_t)(kt + bKr) * 64 + bNo;
            float4 w0 = *(const float4*)(bp);
            float4 w1 = *(const float4*)(bp + 4);
            float vb[8] = {w0.x,w0.y,w0.z,w0.w, w1.x,w1.y,w1.z,w1.w};
            uint32_t ph[4], pl[4];
            float r0, r1;
            #pragma unroll
            for (int e=0;e<4;e++) {
                ph[e] = pack_hi(vb[2*e], vb[2*e+1], r0, r1);
                pl[e] = pack_lo(r0, r1);
            }
            *(uint4*)((char*)B1 + bKr*272 + bNo*2)       = make_uint4(ph[0],ph[1],ph[2],ph[3]);
            *(uint4*)((char*)B1 + bKr*272 + 128 + bNo*2) = make_uint4(pl[0],pl[1],pl[2],pl[3]);
        }
        __syncthreads();

        #pragma unroll
        for (int ks=0; ks<32; ks+=16) {
            wmma::fragment<wmma::matrix_b,16,16,16,bf16,wmma::row_major> bh[2], bl[2];
            #pragma unroll
            for (int nt=0;nt<2;nt++) {
                wmma::load_matrix_sync(bh[nt], &B1[ks*136 + warpN1 + nt*16],      136);
                wmma::load_matrix_sync(bl[nt], &B1[ks*136 + 64 + warpN1 + nt*16], 136);
            }
            #pragma unroll
            for (int mt=0;mt<2;mt++) {
                wmma::fragment<wmma::matrix_a,16,16,16,bf16,wmma::row_major> ah, al;
                wmma::load_matrix_sync(ah, &A1[(warpM1 + mt*16)*72 + ks],      72);
                wmma::load_matrix_sync(al, &A1[(warpM1 + mt*16)*72 + 32 + ks], 72);
                #pragma unroll
                for (int nt=0;nt<2;nt++) {
                    wmma::mma_sync(acc1[mt][nt], ah, bh[nt], acc1[mt][nt]);
                    wmma::mma_sync(acc1[mt][nt], ah, bl[nt], acc1[mt][nt]);
                    wmma::mma_sync(acc1[mt][nt], al, bh[nt], acc1[mt][nt]);
                }
            }
        }
        __syncthreads();
    }

    #pragma unroll
    for (int mt=0;mt<2;mt++)
        #pragma unroll
        for (int nt=0;nt<2;nt++)
            wmma::store_matrix_sync(&STG[(warpM1 + mt*16)*68 + warpN1 + nt*16],
                                    acc1[mt][nt], 68, wmma::mem_row_major);
    __syncthreads();

    {
        int row = tid >> 1, c0 = (tid & 1) * 32;
        #pragma unroll
        for (int e=0;e<32;e++) {
            int col = c0 + e;
            float v = STG[row*68 + col];
            v = tanhf(v + selb[col]);
            STG[row*68 + col] = v;
            bf16 h = __float2bfloat16(v);
            bf16 l = __float2bfloat16(v - __bfloat162float(h));
            LGT[row*136 + col]      = h;
            LGT[row*136 + 64 + col] = l;
        }
    }
    __syncthreads();

    #pragma unroll
    for (int j=0;j<4;j++) {
        int gid = tid*4 + j;
        int row = gid >> 3, mg = gid & 7;
        int b = rowBase + row;
        const float* up = u + (size_t)b*192 + it*64 + mg*8;
        float z[8]; float mx = -3.4e38f;
        #pragma unroll
        for (int k=0;k<8;k++){ z[k] = STG[row*68 + mg*8 + k] + gnoise(up[k]); mx = fmaxf(mx, z[k]); }
        float s = 0.f;
        #pragma unroll
        for (int k=0;k<8;k++){ z[k] = expf(z[k]-mx); s += z[k]; }
        float inv = 1.f/s;
        float* op = g_gsel + (size_t)it*BATCH*64 + (size_t)b*64 + mg*8;
        #pragma unroll
        for (int k=0;k<8;k++) op[k] = z[k]*inv;
    }
    __syncthreads();

    const int warpM2 = (wid >> 2) * 64, warpN2 = (wid & 3) * 32;
    const int bk2 = tid >> 2, bn2 = (tid & 3) * 32;
    const int r  = lane >> 1, cb = (lane & 1) * 16;

    for (int nh = 0; nh < 2; nh++) {
        {
            const float* bp = condW + (size_t)bk2*256 + nh*128 + bn2;
            float vb[32];
            #pragma unroll
            for (int q=0;q<8;q++) {
                float4 w = *(const float4*)(bp + q*4);
                vb[q*4+0]=w.x; vb[q*4+1]=w.y; vb[q*4+2]=w.z; vb[q*4+3]=w.w;
            }
            uint32_t ph[16], pl[16];
            float r0, r1;
            #pragma unroll
            for (int e=0;e<16;e++) {
                ph[e] = pack_hi(vb[2*e], vb[2*e+1], r0, r1);
                pl[e] = pack_lo(r0, r1);
            }
            uint4* dh = (uint4*)((char*)B2 + bk2*528 + bn2*2);
            uint4* dl = (uint4*)((char*)B2 + bk2*528 + 256 + bn2*2);
            #pragma unroll
            for (int q=0;q<4;q++) {
                dh[q] = make_uint4(ph[q*4],ph[q*4+1],ph[q*4+2],ph[q*4+3]);
                dl[q] = make_uint4(pl[q*4],pl[q*4+1],pl[q*4+2],pl[q*4+3]);
            }
        }
        __syncthreads();

        wmma::fragment<wmma::accumulator,16,16,16,float> acc2[4][2];
        #pragma unroll
        for (int mt=0;mt<4;mt++)
            #pragma unroll
            for (int nt=0;nt<2;nt++)
                wmma::fill_fragment(acc2[mt][nt], 0.f);

        #pragma unroll
        for (int ks=0; ks<64; ks+=16) {
            wmma::fragment<wmma::matrix_b,16,16,16,bf16,wmma::row_major> bh[2], bl[2];
            #pragma unroll
            for (int nt=0;nt<2;nt++) {
                wmma::load_matrix_sync(bh[nt], &B2[ks*264 + warpN2 + nt*16],       264);
                wmma::load_matrix_sync(bl[nt], &B2[ks*264 + 128 + warpN2 + nt*16], 264);
            }
            #pragma unroll
            for (int mt=0;mt<4;mt++) {
                wmma::fragment<wmma::matrix_a,16,16,16,bf16,wmma::row_major> ah, al;
                wmma::load_matrix_sync(ah, &LGT[(warpM2 + mt*16)*136 + ks],      136);
                wmma::load_matrix_sync(al, &LGT[(warpM2 + mt*16)*136 + 64 + ks], 136);
                #pragma unroll
                for (int nt=0;nt<2;nt++) {
                    wmma::mma_sync(acc2[mt][nt], ah, bh[nt], acc2[mt][nt]);
                    wmma::mma_sync(acc2[mt][nt], ah, bl[nt], acc2[mt][nt]);
                    wmma::mma_sync(acc2[mt][nt], al, bh[nt], acc2[mt][nt]);
                }
            }
        }
        __syncthreads();

        float* stg2 = (float*)dsm + wid * (16*STG_LD);
        #pragma unroll
        for (int mt=0; mt<4; mt++) {
            wmma::store_matrix_sync(stg2,      acc2[mt][0], STG_LD, wmma::mem_row_major);
            wmma::store_matrix_sync(stg2 + 16, acc2[mt][1], STG_LD, wmma::mem_row_major);
            __syncwarp();
            int row  = rowBase + warpM2 + mt*16 + r;
            int col0 = nh*128 + warpN2 + cb;
            size_t base = (size_t)row * 256 + col0;
            #pragma unroll
            for (int e=0;e<16;e++) {
                float v = stg2[r*STG_LD + cb + e] + condb[col0 + e];
                v *= g_emb[base + e];
                g_si[base + e] = fmaxf(v, 0.f);
            }
            __syncwarp();
        }
        __syncthreads();
    }
}

// ---------------- batchnorm stats (deterministic 2-stage) ----------------
__global__ void colstats(const float* __restrict__ X,
                         float* __restrict__ psum, float* __restrict__ psq,
                         int ncols)
{
    int c = blockIdx.x*256 + threadIdx.x;
    int rpb = BATCH / NPART;
    int r0  = blockIdx.y * rpb;
    float s = 0.f, q = 0.f;
    for (int r = r0; r < r0 + rpb; r++) {
        float v = X[(size_t)r*ncols + c];
        s += v; q += v*v;
    }
    psum[(size_t)blockIdx.y*ncols + c] = s;
    psq [(size_t)blockIdx.y*ncols + c] = q;
}

__global__ void bnfinal(const float* __restrict__ psum, const float* __restrict__ psq,
                        float* __restrict__ mean, float* __restrict__ istd, int n)
{
    int i = blockIdx.x*blockDim.x + threadIdx.x;
    if (i >= n) return;
    float s = 0.f, q = 0.f;
    for (int p = 0; p < NPART; p++) { s += psum[(size_t)p*n + i]; q += psq[(size_t)p*n + i]; }
    float mu  = s * (1.f/BATCH);
    float var = q * (1.f/BATCH) - mu*mu;
    mean[i] = mu;
    istd[i] = rsqrtf(var + 1e-5f);
}

// ---------------- final select logits + fused gumbel ----------------
__global__ void __launch_bounds__(256) gemm_selF(
    const float* __restrict__ W, const float* __restrict__ bias,
    const float* __restrict__ u)
{
    __shared__ float Ws[2048];
    int tid = threadIdx.x;
    for (int idx = tid; idx < 2048; idx += 256) Ws[idx] = W[idx];
    __syncthreads();
    int b = blockIdx.x*32 + (tid >> 3);
    int n = tid & 7;
    const float* ap = g_si + (size_t)b*256;
    float acc = bias[n];
    #pragma unroll 8
    for (int k=0;k<256;k++) acc += ap[k]*Ws[k*8+n];
    float z = acc + gnoise(u[b*8 + n]);
    float mx = z;
    #pragma unroll
    for (int o=1;o<8;o<<=1) mx = fmaxf(mx, __shfl_xor_sync(0xffffffff, mx, o));
    float e = expf(z - mx);
    float s = e;
    #pragma unroll
    for (int o=1;o<8;o<<=1) s += __shfl_xor_sync(0xffffffff, s, o);
    g_fsel[b*8 + n] = e / s;
}

// ---------------- fused bn2 + select cascade + final select + last GEMM ----------------
__global__ void __launch_bounds__(256) cascade(
    const float* __restrict__ g2, const float* __restrict__ b2,
    const float* __restrict__ lastW, const float* __restrict__ lastb,
    float* __restrict__ out)
{
    int b = blockIdx.x;
    int tid = threadIdx.x;
    __shared__ float Ssh[64];
    __shared__ float fs[8];
    __shared__ float ov[256];

    float p[8];
    #pragma unroll
    for (int m=0;m<8;m++) {
        int c = m*256 + tid;
        float v = g_hbig[(size_t)b*2048 + c];
        p[m] = (v - g_mean2[c]) * g_istd2[c] * g2[c] + b2[c];
    }

    for (int l=0;l<3;l++) {
        if (tid < 64) Ssh[tid] = g_gsel[(size_t)(2-l)*BATCH*64 + (size_t)b*64 + tid];
        __syncthreads();
        float np[8];
        #pragma unroll
        for (int m=0;m<8;m++) {
            float a = 0.f;
            #pragma unroll
            for (int k=0;k<8;k++) a += Ssh[m*8+k]*p[k];
            np[m] = fmaxf(a, 0.f);
        }
        #pragma unroll
        for (int m=0;m<8;m++) p[m] = np[m];
        __syncthreads();
    }

    if (tid < 8) fs[tid] = g_fsel[b*8+tid];
    __syncthreads();
    float o = 0.f;
    #pragma unroll
    for (int m=0;m<8;m++) o += fs[m]*p[m];
    ov[tid] = o;
    __syncthreads();

    if (tid < 18) {
        float acc = lastb[tid];
        for (int k=0;k<256;k++) acc += ov[k]*lastW[k*18+tid];
        out[(size_t)b*18 + tid] = acc;
    }
}

// ---------------- launch ----------------
extern "C" void kernel_launch(void* const* d_in, const int* in_sizes, int n_in,
                              void* d_out, int out_size)
{
    const float* x       = (const float*)d_in[0];
    const float* embIn   = (const float*)d_in[1];
    const float* u_sel   = (const float*)d_in[2];
    const float* u_fin   = (const float*)d_in[3];
    const float* base_W0 = (const float*)d_in[4];
    const float* base_b0 = (const float*)d_in[5];
    const float* base_W1 = (const float*)d_in[6];
    const float* base_b1 = (const float*)d_in[7];
    const float* em_W0   = (const float*)d_in[8];
    const float* em_b0   = (const float*)d_in[9];
    const float* gat_W0  = (const float*)d_in[10];
    const float* gat_b0  = (const float*)d_in[11];
    const float* gat_W1  = (const float*)d_in[12];
    const float* gat_b1  = (const float*)d_in[13];
    const float* sel_W   = (const float*)d_in[14];
    const float* sel_b   = (const float*)d_in[15];
    const float* selF_W  = (const float*)d_in[16];
    const float* selF_b  = (const float*)d_in[17];
    const float* cond_W  = (const float*)d_in[18];
    const float* cond_b  = (const float*)d_in[19];
    const float* mod_W   = (const float*)d_in[20];
    const float* last_W  = (const float*)d_in[22];
    const float* last_b  = (const float*)d_in[23];
    const float* bn1_g   = (const float*)d_in[24];
    const float* bn2_g   = (const float*)d_in[26];
    const float* bn2_b   = (const float*)d_in[27];
    float* out = (float*)d_out;

    float *p_h400, *p_h400b, *p_out, *p_tmp, *p_emb, *p_si, *p_hbig;
    float *p_psum1, *p_psq1, *p_psum2, *p_psq2, *p_mean1, *p_istd1, *p_mean2, *p_istd2;
    bf16 *p_outh, *p_outl, *p_W2h, *p_W2l;
    cudaGetSymbolAddress((void**)&p_h400,  g_h400);
    cudaGetSymbolAddress((void**)&p_h400b, g_h400b);
    cudaGetSymbolAddress((void**)&p_out,   g_out);
    cudaGetSymbolAddress((void**)&p_tmp,   g_tmp);
    cudaGetSymbolAddress((void**)&p_emb,   g_emb);
    cudaGetSymbolAddress((void**)&p_si,    g_si);
    cudaGetSymbolAddress((void**)&p_hbig,  g_hbig);
    cudaGetSymbolAddress((void**)&p_psum1, g_psum1);
    cudaGetSymbolAddress((void**)&p_psq1,  g_psq1);
    cudaGetSymbolAddress((void**)&p_psum2, g_psum2);
    cudaGetSymbolAddress((void**)&p_psq2,  g_psq2);
    cudaGetSymbolAddress((void**)&p_mean1, g_mean1);
    cudaGetSymbolAddress((void**)&p_istd1, g_istd1);
    cudaGetSymbolAddress((void**)&p_mean2, g_mean2);
    cudaGetSymbolAddress((void**)&p_istd2, g_istd2);
    cudaGetSymbolAddress((void**)&p_outh,  g_outh);
    cudaGetSymbolAddress((void**)&p_outl,  g_outl);
    cudaGetSymbolAddress((void**)&p_W2h,   g_W2h);
    cudaGetSymbolAddress((void**)&p_W2l,   g_W2l);

    cudaFuncSetAttribute(selstep, cudaFuncAttributeMaxDynamicSharedMemorySize, 69632);

    static cudaStream_t s1 = nullptr;
    static cudaEvent_t evFork = nullptr, evJoin = nullptr, evW = nullptr;
    if (s1 == nullptr) {
        cudaStreamCreateWithFlags(&s1, cudaStreamNonBlocking);
        cudaEventCreateWithFlags(&evFork, cudaEventDisableTiming);
        cudaEventCreateWithFlags(&evJoin, cudaEventDisableTiming);
        cudaEventCreateWithFlags(&evW,    cudaEventDisableTiming);
    }

    dim3 blk(256);
    auto grid2 = [](int N){ return dim3((unsigned)((N+127)/128), BATCH/128); };

    // ---- fork ----
    cudaEventRecord(evFork, 0);
    cudaStreamWaitEvent(s1, evFork, 0);

    // ===== branch B (stream 1): W2 prep + emb chain + select loop + selF =====
    scaleW<<<2048, blk, 0, s1>>>(mod_W, bn1_g);     // no batch-data deps
    cudaEventRecord(evW, s1);
    tgemm_tc<<<grid2(400), blk, 0, s1>>>(embIn,   em_W0,  em_b0,  p_h400b, nullptr, nullptr, 400, 128, EPI_RELU);
    tgemm_tc<<<grid2(256), blk, 0, s1>>>(p_h400b, gat_W0, gat_b0, p_tmp,   nullptr, nullptr, 256, 400, EPI_RELU);
    tgemm_tc<<<grid2(256), blk, 0, s1>>>(p_tmp,   gat_W1, gat_b1, p_emb,   p_si,    nullptr, 256, 256, EPI_DUAL);
    for (int i = 0; i < 3; i++) {
        selstep<<<BATCH/128, blk, 69632, s1>>>(sel_W + (size_t)i*256*64, sel_b + i*64,
                                               cond_W + (size_t)i*64*256, cond_b + i*256,
                                               u_sel, i);
    }
    gemm_selF<<<BATCH/32, blk, 0, s1>>>(selF_W, selF_b, u_fin);
    cudaEventRecord(evJoin, s1);

    // ===== branch A (main stream): base chain -> bn1 -> cvt -> mod GEMM -> bn2 =====
    tgemm_tc<<<grid2(400), blk, 0, 0>>>(x,      base_W0, base_b0, p_h400, nullptr, nullptr, 400, 128, EPI_RELU);
    tgemm_tc<<<grid2(256), blk, 0, 0>>>(p_h400, base_W1, base_b1, p_out,  nullptr, nullptr, 256, 400, EPI_NONE);
    colstats<<<dim3(1, NPART), blk, 0, 0>>>(p_out, p_psum1, p_psq1, 256);
    bnfinal<<<1, blk, 0, 0>>>(p_psum1, p_psq1, p_mean1, p_istd1, 256);
    cvt_out<<<BATCH, blk, 0, 0>>>();                 // out*istd1, split
    cudaStreamWaitEvent(0, evW, 0);                  // W2 ready
    tgemm_pre<<<grid2(2048), blk, 0, 0>>>(p_outh, p_outl, p_W2h, p_W2l, p_hbig, 2048, 256);
    colstats<<<dim3(8, NPART), blk, 0, 0>>>(p_hbig, p_psum2, p_psq2, 2048);
    bnfinal<<<8, blk, 0, 0>>>(p_psum2, p_psq2, p_mean2, p_istd2, 2048);

    // ---- join, then final fused kernel ----
    cudaStreamWaitEvent(0, evJoin, 0);
    cascade<<<BATCH, blk, 0, 0>>>(bn2_g, bn2_b, last_W, last_b, out);
}